// round 11
// baseline (speedup 1.0000x reference)
#include <cuda_runtime.h>
#include <cuda_fp16.h>

#define OC_N       32
#define TPO        144              // tables per output channel
#define TPB        72               // tables per block (table-half split)
#define IC_N       16
#define PH         34
#define PW         34
#define CH_STRIDE  (PH*PW)          // 1156
#define TILE_ELEMS (IC_N*CH_STRIDE) // 18496 elements
#define NTHREADS   256
#define ROWOFF     (8*PW*2)         // 544 B: +8 rows (LDS immediate offset)

// Zero the output (it is poisoned; partial blocks RED-add into it).
__global__ void zero_out(float4* __restrict__ o) {
    o[blockIdx.x * 256 + threadIdx.x] = make_float4(0.f, 0.f, 0.f, 0.f);
}

// Block = (batch, oc, table-half). 256 threads, 4 positions/thread
// (x-pair at rows r and r+8 via LDS immediate). Tile fp16, two parity copies.
// Each block RED-adds its 72-table partial sums into out; th=0 blocks also
// add the per-oc constant A to ALL FOUR of their positions.
extern __shared__ float smem[];

__global__ void __launch_bounds__(NTHREADS, 3)
lutconv_fused(const float*  __restrict__ inp,
              const float4* __restrict__ w4,
              const int*    __restrict__ mc,
              const int*    __restrict__ mkh,
              const int*    __restrict__ mkw,
              float*        __restrict__ out) {
    const int bid = blockIdx.x;
    const int b   = bid >> 6;         // batch
    const int r6  = bid & 63;
    const int oc  = r6 >> 1;          // output channel
    const int th  = r6 & 1;           // table half
    const int tid = threadIdx.x;

    __half* ht    = (__half*)smem;                      // [2*TILE_ELEMS]
    float4* srec  = (float4*)(smem + TILE_ELEMS);       // [TPB]
    float*  sA    = (float*)(srec + TPB);               // [1]

    // --- Per-table precompute for this block's 72 tables
    if (tid < TPB) {
        const int t = oc*TPO + th*TPB + tid;
        const float4 wv = w4[t];
        const float bco = 0.25f * (-wv.x + wv.y - wv.z + wv.w);
        const float cco = 0.25f * (-wv.x - wv.y + wv.z + wv.w);
        const float dco = 0.25f * ( wv.x - wv.y - wv.z + wv.w);
        const int m0 = 2*t;
        unsigned o0 = (unsigned)(mc[m0  ]*CH_STRIDE + mkh[m0  ]*PW + mkw[m0  ]);
        unsigned o1 = (unsigned)(mc[m0+1]*CH_STRIDE + mkh[m0+1]*PW + mkw[m0+1]);
        o0 = (o0 & 1u) ? (unsigned)TILE_ELEMS + o0 - 1u : o0;   // odd -> copy B
        o1 = (o1 & 1u) ? (unsigned)TILE_ELEMS + o1 - 1u : o1;
        const __half2 bb = __float2half2_rn(bco);
        const __half2 cc = __float2half2_rn(cco);
        const __half2 dd = __float2half2_rn(dco);
        float4 p;
        p.x = __uint_as_float(o0 | (o1 << 16));
        p.y = *(const float*)&bb;
        p.z = *(const float*)&cc;
        p.w = *(const float*)&dd;
        srec[tid] = p;
    }

    // --- Per-oc constant A (only th=0 blocks add it), direct LDG reduce
    if (th == 0 && tid >= 32 && tid < 64) {
        const int l = tid - 32;
        float s = 0.0f;
        #pragma unroll
        for (int i = 0; i < TPO; i += 32) {
            if (l + i < TPO) {
                const float4 wv = w4[oc*TPO + l + i];
                s += wv.x + wv.y + wv.z + wv.w;
            }
        }
        #pragma unroll
        for (int d = 16; d; d >>= 1) s += __shfl_xor_sync(0xffffffffu, s, d);
        if (l == 0) *sA = 0.25f * s;
    }
    if (th == 1 && tid == 32) *sA = 0.0f;

    // --- Zero both fp16 tile copies
    {
        const float4 z4 = make_float4(0.f, 0.f, 0.f, 0.f);
        float4* t4 = (float4*)ht;
        #pragma unroll
        for (int i = tid; i < (2*TILE_ELEMS*2)/16; i += NTHREADS) t4[i] = z4;
    }
    __syncthreads();

    // --- Stage interior: f32 -> f16, copy A at e, copy B at e-1
    {
        const float4* ib4 = (const float4*)(inp + (size_t)b * (IC_N*32*32));
        #pragma unroll
        for (int i = tid; i < 4096; i += NTHREADS) {    // 16 iterations
            const float4 v = ib4[i];
            const int j = i << 2;
            const int c = j >> 10;
            const int y = (j >> 5) & 31;
            const int x = j & 31;
            const int e = c*CH_STRIDE + (y+1)*PW + (x+1);
            const __half h0 = __float2half(v.x);
            const __half h1 = __float2half(v.y);
            const __half h2 = __float2half(v.z);
            const __half h3 = __float2half(v.w);
            ht[e  ] = h0; ht[e+1] = h1; ht[e+2] = h2; ht[e+3] = h3;
            ht[TILE_ELEMS + e-1] = h0; ht[TILE_ELEMS + e  ] = h1;
            ht[TILE_ELEMS + e+1] = h2; ht[TILE_ELEMS + e+2] = h3;
        }
    }
    __syncthreads();

    // --- Main loop: 4 positions/thread, 72 tables.
    const int l    = tid & 31;
    const int wrp  = tid >> 5;                     // 0..7
    const int rowA = wrp + ((l >> 4) << 4);        // wrp or wrp+16
    const int x    = (l & 15) << 1;
    const char* tb = (const char*)ht + (rowA*PW + x)*2;

    float f00 = 0.f, f01 = 0.f, f10 = 0.f, f11 = 0.f;

    #pragma unroll 2
    for (int t = 0; t < TPB; t += 2) {
        const float4 pa = srec[t];
        const float4 pb = srec[t+1];
        const unsigned ua = __float_as_uint(pa.x);
        const unsigned ub = __float_as_uint(pb.x);
        const char* a0 = tb + (ua & 0xffffu)*2u;
        const char* a1 = tb + (ua >> 16)*2u;
        const char* b0 = tb + (ub & 0xffffu)*2u;
        const char* b1 = tb + (ub >> 16)*2u;

        const __half2 xa0 = *(const __half2*)(a0);
        const __half2 xa1 = *(const __half2*)(a1);
        const __half2 ya0 = *(const __half2*)(a0 + ROWOFF);
        const __half2 ya1 = *(const __half2*)(a1 + ROWOFF);
        const __half2 xb0 = *(const __half2*)(b0);
        const __half2 xb1 = *(const __half2*)(b1);
        const __half2 yb0 = *(const __half2*)(b0 + ROWOFF);
        const __half2 yb1 = *(const __half2*)(b1 + ROWOFF);

        const __half2 Ba = *(const __half2*)&pa.y;
        const __half2 Ca = *(const __half2*)&pa.z;
        const __half2 Da = *(const __half2*)&pa.w;
        const __half2 Bb = *(const __half2*)&pb.y;
        const __half2 Cb = *(const __half2*)&pb.z;
        const __half2 Db = *(const __half2*)&pb.w;

        __half2 acc01 = __hmul2(Ca, xa1);
        acc01 = __hfma2(xa0, __hfma2(Da, xa1, Ba), acc01);
        acc01 = __hfma2(Cb, xb1, acc01);
        acc01 = __hfma2(xb0, __hfma2(Db, xb1, Bb), acc01);

        __half2 acc23 = __hmul2(Ca, ya1);
        acc23 = __hfma2(ya0, __hfma2(Da, ya1, Ba), acc23);
        acc23 = __hfma2(Cb, yb1, acc23);
        acc23 = __hfma2(yb0, __hfma2(Db, yb1, Bb), acc23);

        const float2 fa = __half22float2(acc01);
        f00 += fa.x; f01 += fa.y;
        const float2 fb = __half22float2(acc23);
        f10 += fb.x; f11 += fb.y;
    }

    const float A = *sA;     // A_oc for th=0 blocks, 0 for th=1 blocks
    float* ob = out + ((size_t)(b*OC_N + oc)) * 1024;
    float* p0 = ob + rowA*32 + x;
    float* p1 = ob + (rowA+8)*32 + x;
    atomicAdd(p0,     f00 + A);
    atomicAdd(p0 + 1, f01 + A);
    atomicAdd(p1,     f10 + A);   // FIX (R10 bug): A applies to ALL positions
    atomicAdd(p1 + 1, f11 + A);
}

// ---------------------------------------------------------------------------
extern "C" void kernel_launch(void* const* d_in, const int* in_sizes, int n_in,
                              void* d_out, int out_size) {
    const float*  inp = (const float*)d_in[0];
    const float4* w4  = (const float4*)d_in[1];
    const int*    mc  = (const int*)d_in[2];
    const int*    mkh = (const int*)d_in[3];
    const int*    mkw = (const int*)d_in[4];
    float*        out = (float*)d_out;

    // out = 8*32*1024 floats = 65536 float4s
    zero_out<<<256, 256>>>((float4*)out);

    const int smem_bytes = 2*TILE_ELEMS*(int)sizeof(__half)  // 73984
                         + TPB*(int)sizeof(float4)           // 1152
                         + 16;                               // sA+pad -> 75152 B
    cudaFuncSetAttribute(lutconv_fused,
                         cudaFuncAttributeMaxDynamicSharedMemorySize, smem_bytes);
    lutconv_fused<<<8*OC_N*2, NTHREADS, smem_bytes>>>(inp, w4, mc, mkh, mkw, out);
}

// round 13
// speedup vs baseline: 1.7324x; 1.7324x over previous
#include <cuda_runtime.h>
#include <cuda_fp16.h>

#define OC_N       32
#define TPO        144              // tables per output channel
#define IC_N       16
#define PH         34
#define PW         34
#define CH_STRIDE  (PH*PW)          // 1156
#define TILE_ELEMS (IC_N*CH_STRIDE) // 18496 elements
#define NTHREADS   256
#define ROWOFF     (8*PW*2)         // 544 B: +8 rows (LDS immediate offset)

// Block = (batch, oc), 256 threads. Each thread evaluates 4 positions:
// half2 pair (row, x..x+1) and (row+8, x..x+1) via LDS immediate offset.
// Tile fp16 with TWO parity copies so every pair load is one aligned LDS.32.
// Main loop: 4 tables/iter, ALL 4 records + 16 data loads hoisted for ILP.
extern __shared__ float smem[];

__global__ void __launch_bounds__(NTHREADS, 2)
lutconv_fused(const float*  __restrict__ inp,
              const float4* __restrict__ w4,
              const int*    __restrict__ mc,
              const int*    __restrict__ mkh,
              const int*    __restrict__ mkw,
              float*        __restrict__ out) {
    const int b   = blockIdx.x >> 5;
    const int oc  = blockIdx.x & 31;
    const int tid = threadIdx.x;

    __half* ht    = (__half*)smem;                      // [2*TILE_ELEMS]
    float4* srec  = (float4*)(smem + TILE_ELEMS);       // [TPO]
    float*  scw   = (float*)(srec + TPO);               // [TPO]
    float*  sA    = scw + TPO;                          // [1]

    // --- Per-table precompute
    if (tid < TPO) {
        const int t = oc*TPO + tid;
        const float4 wv = w4[t];
        const float bco = 0.25f * (-wv.x + wv.y - wv.z + wv.w);
        const float cco = 0.25f * (-wv.x - wv.y + wv.z + wv.w);
        const float dco = 0.25f * ( wv.x - wv.y - wv.z + wv.w);
        const float aco = 0.25f * ( wv.x + wv.y + wv.z + wv.w);
        const int m0 = 2*t;
        unsigned o0 = (unsigned)(mc[m0  ]*CH_STRIDE + mkh[m0  ]*PW + mkw[m0  ]);
        unsigned o1 = (unsigned)(mc[m0+1]*CH_STRIDE + mkh[m0+1]*PW + mkw[m0+1]);
        o0 = (o0 & 1u) ? (unsigned)TILE_ELEMS + o0 - 1u : o0;   // odd -> copy B
        o1 = (o1 & 1u) ? (unsigned)TILE_ELEMS + o1 - 1u : o1;
        const __half2 bb = __float2half2_rn(bco);
        const __half2 cc = __float2half2_rn(cco);
        const __half2 dd = __float2half2_rn(dco);
        float4 p;
        p.x = __uint_as_float(o0 | (o1 << 16));
        p.y = *(const float*)&bb;
        p.z = *(const float*)&cc;
        p.w = *(const float*)&dd;
        srec[tid] = p;
        scw[tid]  = aco;
    }

    // --- Zero both fp16 tile copies
    {
        const float4 z4 = make_float4(0.f, 0.f, 0.f, 0.f);
        float4* t4 = (float4*)ht;
        #pragma unroll
        for (int i = tid; i < (2*TILE_ELEMS*2)/16; i += NTHREADS) t4[i] = z4;
    }
    __syncthreads();

    // --- Stage interior: f32 -> f16, copy A at e, copy B at e-1
    {
        const float4* ib4 = (const float4*)(inp + (size_t)b * (IC_N*32*32));
        #pragma unroll
        for (int i = tid; i < 4096; i += NTHREADS) {    // 16 iterations
            const float4 v = ib4[i];
            const int j = i << 2;
            const int c = j >> 10;
            const int y = (j >> 5) & 31;
            const int x = j & 31;
            const int e = c*CH_STRIDE + (y+1)*PW + (x+1);
            const __half h0 = __float2half(v.x);
            const __half h1 = __float2half(v.y);
            const __half h2 = __float2half(v.z);
            const __half h3 = __float2half(v.w);
            ht[e  ] = h0; ht[e+1] = h1; ht[e+2] = h2; ht[e+3] = h3;
            ht[TILE_ELEMS + e-1] = h0; ht[TILE_ELEMS + e  ] = h1;
            ht[TILE_ELEMS + e+1] = h2; ht[TILE_ELEMS + e+2] = h3;
        }
    }
    __syncthreads();

    // --- Per-oc constant term
    if (tid < 32) {
        float s = scw[tid] + scw[tid+32] + scw[tid+64] + scw[tid+96]
                + (tid < (TPO - 128) ? scw[tid+128] : 0.0f);
        #pragma unroll
        for (int d = 16; d; d >>= 1) s += __shfl_xor_sync(0xffffffffu, s, d);
        if (tid == 0) *sA = s;
    }
    __syncthreads();

    // --- Main loop: 4 tables/iter, loads hoisted.
    const int l    = tid & 31;
    const int wrp  = tid >> 5;                     // 0..7
    const int rowA = wrp + ((l >> 4) << 4);        // wrp or wrp+16
    const int x    = (l & 15) << 1;
    const char* tb = (const char*)ht + (rowA*PW + x)*2;

    float f00 = 0.f, f01 = 0.f, f10 = 0.f, f11 = 0.f;

    for (int t = 0; t < TPO; t += 4) {
        float4 p[4];
        p[0] = srec[t]; p[1] = srec[t+1]; p[2] = srec[t+2]; p[3] = srec[t+3];

        const char* a0[4]; const char* a1[4];
        #pragma unroll
        for (int i = 0; i < 4; ++i) {
            const unsigned u = __float_as_uint(p[i].x);
            a0[i] = tb + (u & 0xffffu)*2u;
            a1[i] = tb + (u >> 16)*2u;
        }

        __half2 x0[4], x1[4], y0[4], y1[4];
        #pragma unroll
        for (int i = 0; i < 4; ++i) {
            x0[i] = *(const __half2*)(a0[i]);
            x1[i] = *(const __half2*)(a1[i]);
            y0[i] = *(const __half2*)(a0[i] + ROWOFF);
            y1[i] = *(const __half2*)(a1[i] + ROWOFF);
        }

        #pragma unroll
        for (int g = 0; g < 2; ++g) {              // 2-table groups (numerics = R9)
            const int i0 = 2*g, i1 = 2*g + 1;
            const __half2 Ba = *(const __half2*)&p[i0].y;
            const __half2 Ca = *(const __half2*)&p[i0].z;
            const __half2 Da = *(const __half2*)&p[i0].w;
            const __half2 Bb = *(const __half2*)&p[i1].y;
            const __half2 Cb = *(const __half2*)&p[i1].z;
            const __half2 Db = *(const __half2*)&p[i1].w;

            __half2 acc01 = __hmul2(Ca, x1[i0]);
            acc01 = __hfma2(x0[i0], __hfma2(Da, x1[i0], Ba), acc01);
            acc01 = __hfma2(Cb, x1[i1], acc01);
            acc01 = __hfma2(x0[i1], __hfma2(Db, x1[i1], Bb), acc01);

            __half2 acc23 = __hmul2(Ca, y1[i0]);
            acc23 = __hfma2(y0[i0], __hfma2(Da, y1[i0], Ba), acc23);
            acc23 = __hfma2(Cb, y1[i1], acc23);
            acc23 = __hfma2(y0[i1], __hfma2(Db, y1[i1], Bb), acc23);

            const float2 fa = __half22float2(acc01);
            f00 += fa.x; f01 += fa.y;
            const float2 fb = __half22float2(acc23);
            f10 += fb.x; f11 += fb.y;
        }
    }

    const float A = *sA;
    float* ob = out + ((size_t)(b*OC_N + oc)) * 1024;
    float2 r0; r0.x = f00 + A; r0.y = f01 + A;
    float2 r1; r1.x = f10 + A; r1.y = f11 + A;
    *(float2*)(ob + rowA*32 + x)     = r0;
    *(float2*)(ob + (rowA+8)*32 + x) = r1;
}

// ---------------------------------------------------------------------------
extern "C" void kernel_launch(void* const* d_in, const int* in_sizes, int n_in,
                              void* d_out, int out_size) {
    const float*  inp = (const float*)d_in[0];
    const float4* w4  = (const float4*)d_in[1];
    const int*    mc  = (const int*)d_in[2];
    const int*    mkh = (const int*)d_in[3];
    const int*    mkw = (const int*)d_in[4];
    float*        out = (float*)d_out;

    const int smem_bytes = 2*TILE_ELEMS*(int)sizeof(__half)  // 73984
                         + TPO*(int)sizeof(float4)           // 2304
                         + (TPO + 1)*(int)sizeof(float);     // 580 -> 76868 B
    cudaFuncSetAttribute(lutconv_fused,
                         cudaFuncAttributeMaxDynamicSharedMemorySize, smem_bytes);
    lutconv_fused<<<8*OC_N, NTHREADS, smem_bytes>>>(inp, w4, mc, mkh, mkw, out);
}